// round 4
// baseline (speedup 1.0000x reference)
#include <cuda_runtime.h>
#include <cuda_bf16.h>

#define N_NODES 1024
#define EDIM 16

typedef unsigned long long u64;

// ---------------- packed f32x2 helpers (sm_103a) ----------------
__device__ __forceinline__ u64 pack2(float lo, float hi) {
    u64 r; asm("mov.b64 %0, {%1, %2};" : "=l"(r) : "f"(lo), "f"(hi)); return r;
}
__device__ __forceinline__ void unpack2(u64 v, float& lo, float& hi) {
    asm("mov.b64 {%0, %1}, %2;" : "=f"(lo), "=f"(hi) : "l"(v));
}
__device__ __forceinline__ u64 ffma2(u64 a, u64 b, u64 c) {
    u64 d; asm("fma.rn.f32x2 %0, %1, %2, %3;" : "=l"(d) : "l"(a), "l"(b), "l"(c)); return d;
}
__device__ __forceinline__ u64 add2(u64 a, u64 b) {
    u64 d; asm("add.rn.f32x2 %0, %1, %2;" : "=l"(d) : "l"(a), "l"(b)); return d;
}

// ---------------- constant biases only (always lane-uniform access) ----------------
__constant__ float cbe1[16];
__constant__ float cbe2[16];
__constant__ float cbn1[32];
__constant__ float cbn2[32];

// ---------------- device scratch ----------------
__device__ __align__(16) float g_pa[N_NODES * EDIM];
__device__ __align__(16) float g_pb[N_NODES * EDIM];
__device__ __align__(16) float g_msga[N_NODES * EDIM];
__device__ __align__(16) float g_msgb[N_NODES * EDIM];

// ============ Kernel A: zero accumulators + per-node precompute ============
// 8 blocks x 256 threads. Blocks 0-3: pa (nodes), stage We1 rows 0..31.
// Blocks 4-7: pb, stage We1 rows 32..63. Weights via smem (no divergent LDC).
__global__ __launch_bounds__(256) void prep_kernel(const float* __restrict__ na,
                                                   const float* __restrict__ nb,
                                                   const float* __restrict__ We1) {
    __shared__ __align__(16) float sw[32 * 16];

    const int b   = blockIdx.x;
    const bool isA = (b < 4);
    const int bb  = isA ? b : b - 4;
    const int tid = threadIdx.x;
    const int node = bb * 256 + tid;

    // stage 512 weight floats (coalesced from global)
    reinterpret_cast<float2*>(sw)[tid] =
        reinterpret_cast<const float2*>(We1 + (isA ? 0 : 512))[tid];

    // zero message accumulators: each block zeroes 4096 floats of one array
    {
        float4* z = reinterpret_cast<float4*>((isA ? g_msga : g_msgb) + bb * 4096);
#pragma unroll
        for (int q = 0; q < 4; q++) z[tid * 4 + q] = make_float4(0.f, 0.f, 0.f, 0.f);
    }
    __syncthreads();

    // load node row
    const float* row = (isA ? na : nb) + node * 32;
    float x[32];
#pragma unroll
    for (int u = 0; u < 8; u++) {
        float4 v = reinterpret_cast<const float4*>(row)[u];
        x[u * 4 + 0] = v.x; x[u * 4 + 1] = v.y; x[u * 4 + 2] = v.z; x[u * 4 + 3] = v.w;
    }

    float acc[16];
#pragma unroll
    for (int c = 0; c < 16; c++) acc[c] = isA ? cbe1[c] : 0.0f;

#pragma unroll
    for (int k = 0; k < 32; k++) {
        const float xs = x[k];
#pragma unroll
        for (int q = 0; q < 4; q++) {
            float4 w = reinterpret_cast<const float4*>(&sw[k * 16])[q];  // uniform LDS.128
            acc[q * 4 + 0] = fmaf(xs, w.x, acc[q * 4 + 0]);
            acc[q * 4 + 1] = fmaf(xs, w.y, acc[q * 4 + 1]);
            acc[q * 4 + 2] = fmaf(xs, w.z, acc[q * 4 + 2]);
            acc[q * 4 + 3] = fmaf(xs, w.w, acc[q * 4 + 3]);
        }
    }

    float* dst = (isA ? g_pa : g_pb) + node * 16;
#pragma unroll
    for (int q = 0; q < 4; q++)
        reinterpret_cast<float4*>(dst)[q] =
            make_float4(acc[q * 4], acc[q * 4 + 1], acc[q * 4 + 2], acc[q * 4 + 3]);
}

// Butterfly channel-merging reduction: 16 channels x 32 lanes in 16 shfls.
__device__ __forceinline__ int chan16(int lane) {
    return ((lane & 1) ? 8 : 0) | ((lane & 2) ? 4 : 0) |
           ((lane & 4) ? 2 : 0) | ((lane & 8) ? 1 : 0);
}

__device__ __forceinline__ float warp_reduce16(float* v, int lane) {
    const unsigned FULL = 0xffffffffu;
    {
        bool hi = (lane & 1);
#pragma unroll
        for (int k = 0; k < 8; k++) {
            float send  = hi ? v[k] : v[k + 8];
            float other = __shfl_xor_sync(FULL, send, 1);
            v[k] = (hi ? v[k + 8] : v[k]) + other;
        }
    }
    {
        bool hi = (lane & 2);
#pragma unroll
        for (int k = 0; k < 4; k++) {
            float send  = hi ? v[k] : v[k + 4];
            float other = __shfl_xor_sync(FULL, send, 2);
            v[k] = (hi ? v[k + 4] : v[k]) + other;
        }
    }
    {
        bool hi = (lane & 4);
#pragma unroll
        for (int k = 0; k < 2; k++) {
            float send  = hi ? v[k] : v[k + 2];
            float other = __shfl_xor_sync(FULL, send, 4);
            v[k] = (hi ? v[k + 2] : v[k]) + other;
        }
    }
    {
        bool hi = (lane & 8);
        float send  = hi ? v[0] : v[1];
        float other = __shfl_xor_sync(FULL, send, 8);
        v[0] = (hi ? v[1] : v[0]) + other;
    }
    v[0] += __shfl_xor_sync(FULL, v[0], 16);
    return v[0];
}

// ============ Kernel B: edge MLP + fused message aggregation ============
// Block: 256 threads = 256 consecutive j; block covers 8 i-rows.
// Weights live in SMEM (uniform broadcast LDS.128); math in packed f32x2.
__global__ __launch_bounds__(256, 2) void edge_kernel(const float* __restrict__ edges,
                                                      const float* __restrict__ We1,
                                                      const float* __restrict__ We2,
                                                      float* __restrict__ out_e) {
    __shared__ __align__(16) float s_w1[32 * 16];   // We1 rows 64..95 (edge part)
    __shared__ __align__(16) float s_w2[16 * 16];   // We2
    __shared__ __align__(16) float s_pa[8 * 16];

    const int tid  = threadIdx.x;
    const int lane = tid & 31;
    const int j    = blockIdx.x * 256 + tid;
    const int i0   = blockIdx.y * 8;

    // stage weights (coalesced from global) + pa rows
    if (tid < 128) {
        reinterpret_cast<float4*>(s_w1)[tid] =
            reinterpret_cast<const float4*>(We1 + 64 * 16)[tid];
        s_pa[tid] = g_pa[i0 * 16 + tid];
    } else if (tid < 192) {
        const int t = tid - 128;
        reinterpret_cast<float4*>(s_w2)[t] = reinterpret_cast<const float4*>(We2)[t];
    }

    // pb packed channel pairs
    u64 pb2[8];
    {
        const float4* p4 = reinterpret_cast<const float4*>(g_pb + j * 16);
#pragma unroll
        for (int u = 0; u < 4; u++) {
            float4 v = p4[u];
            pb2[2 * u]     = pack2(v.x, v.y);
            pb2[2 * u + 1] = pack2(v.z, v.w);
        }
    }
    // be2 packed (uniform constant access)
    u64 be2p[8];
#pragma unroll
    for (int p = 0; p < 8; p++) be2p[p] = pack2(cbe2[2 * p], cbe2[2 * p + 1]);

    float msgb[16];
#pragma unroll
    for (int c = 0; c < 16; c++) msgb[c] = 0.0f;

    __syncthreads();

#pragma unroll 1
    for (int ir = 0; ir < 8; ir++) {
        const int i = i0 + ir;

        // load this edge's 32 features (8 x LDG.128)
        const float4* xp = reinterpret_cast<const float4*>(edges + ((size_t)i * 1024 + j) * 32);
        float4 xv[8];
#pragma unroll
        for (int u = 0; u < 8; u++) xv[u] = xp[u];

        // init h with pa[i] + pb[j] (packed)
        u64 h2[8];
        {
            const ulonglong2* par = reinterpret_cast<const ulonglong2*>(&s_pa[ir * 16]);
#pragma unroll
            for (int q = 0; q < 4; q++) {
                ulonglong2 pa = par[q];             // uniform LDS.128
                h2[2 * q]     = add2(pa.x, pb2[2 * q]);
                h2[2 * q + 1] = add2(pa.y, pb2[2 * q + 1]);
            }
        }

        // layer 1: h += edge @ We1[64:96]
#pragma unroll
        for (int u = 0; u < 8; u++) {
            const float4 v = xv[u];
#pragma unroll
            for (int kk = 0; kk < 4; kk++) {
                const float xs = (kk == 0) ? v.x : (kk == 1) ? v.y : (kk == 2) ? v.z : v.w;
                const u64 xs2 = pack2(xs, xs);
                const ulonglong2* w =
                    reinterpret_cast<const ulonglong2*>(&s_w1[(u * 4 + kk) * 16]);
#pragma unroll
                for (int q = 0; q < 4; q++) {
                    ulonglong2 wq = w[q];           // uniform LDS.128
                    h2[2 * q]     = ffma2(xs2, wq.x, h2[2 * q]);
                    h2[2 * q + 1] = ffma2(xs2, wq.y, h2[2 * q + 1]);
                }
            }
        }

        // relu + unpack
        float h[16];
#pragma unroll
        for (int p = 0; p < 8; p++) {
            float lo, hi; unpack2(h2[p], lo, hi);
            h[2 * p]     = fmaxf(lo, 0.0f);
            h[2 * p + 1] = fmaxf(hi, 0.0f);
        }

        // layer 2
        u64 e2[8];
#pragma unroll
        for (int p = 0; p < 8; p++) e2[p] = be2p[p];
#pragma unroll
        for (int k = 0; k < 16; k++) {
            const u64 hs = pack2(h[k], h[k]);
            const ulonglong2* w = reinterpret_cast<const ulonglong2*>(&s_w2[k * 16]);
#pragma unroll
            for (int q = 0; q < 4; q++) {
                ulonglong2 wq = w[q];
                e2[2 * q]     = ffma2(hs, wq.x, e2[2 * q]);
                e2[2 * q + 1] = ffma2(hs, wq.y, e2[2 * q + 1]);
            }
        }

        // relu
        float e[16];
#pragma unroll
        for (int p = 0; p < 8; p++) {
            float lo, hi; unpack2(e2[p], lo, hi);
            e[2 * p]     = fmaxf(lo, 0.0f);
            e[2 * p + 1] = fmaxf(hi, 0.0f);
        }

        // store new_edges[i][j][:]
        float4* op = reinterpret_cast<float4*>(out_e + ((size_t)i * 1024 + j) * 16);
#pragma unroll
        for (int q = 0; q < 4; q++)
            op[q] = make_float4(e[4 * q], e[4 * q + 1], e[4 * q + 2], e[4 * q + 3]);

        // msg_b: register accumulate
#pragma unroll
        for (int c = 0; c < 16; c++) msgb[c] += e[c];

        // msg_a: butterfly reduce + 16-lane spread atomics
        float total = warp_reduce16(e, lane);
        if (lane < 16) atomicAdd(&g_msga[i * 16 + chan16(lane)], total);
    }

#pragma unroll
    for (int c = 0; c < 16; c++) atomicAdd(&g_msgb[j * 16 + c], msgb[c]);
}

// ============ Kernel C: node MLP (weights via smem) ============
__global__ __launch_bounds__(128) void node_kernel(const float* __restrict__ na,
                                                   const float* __restrict__ nb,
                                                   const float* __restrict__ Wn1,
                                                   const float* __restrict__ Wn2,
                                                   float* __restrict__ out_a,
                                                   float* __restrict__ out_b) {
    __shared__ __align__(16) float s1[48 * 32];
    __shared__ __align__(16) float s2[32 * 32];

    const int tid = threadIdx.x;
    // stage: 1536 + 1024 floats with 128 threads (float4 vectorized, coalesced)
#pragma unroll
    for (int q = 0; q < 3; q++)
        reinterpret_cast<float4*>(s1)[tid * 3 + q] = reinterpret_cast<const float4*>(Wn1)[tid * 3 + q];
#pragma unroll
    for (int q = 0; q < 2; q++)
        reinterpret_cast<float4*>(s2)[tid * 2 + q] = reinterpret_cast<const float4*>(Wn2)[tid * 2 + q];
    __syncthreads();

    const int r = blockIdx.x * 128 + tid;
    const float* node;
    const float* msg;
    float* out;
    if (r < N_NODES) {
        node = na + r * 32;  msg = g_msga + r * 16;  out = out_a + r * 32;
    } else {
        int rr = r - N_NODES;
        node = nb + rr * 32; msg = g_msgb + rr * 16; out = out_b + rr * 32;
    }

    float x[48];
#pragma unroll
    for (int u = 0; u < 8; u++) {
        float4 v = reinterpret_cast<const float4*>(node)[u];
        x[u * 4 + 0] = v.x; x[u * 4 + 1] = v.y; x[u * 4 + 2] = v.z; x[u * 4 + 3] = v.w;
    }
#pragma unroll
    for (int u = 0; u < 4; u++) {
        float4 v = reinterpret_cast<const float4*>(msg)[u];
        x[32 + u * 4 + 0] = v.x; x[32 + u * 4 + 1] = v.y;
        x[32 + u * 4 + 2] = v.z; x[32 + u * 4 + 3] = v.w;
    }

    float h[32];
#pragma unroll
    for (int c = 0; c < 32; c++) h[c] = cbn1[c];
#pragma unroll
    for (int k = 0; k < 48; k++) {
        const float xs = x[k];
#pragma unroll
        for (int q = 0; q < 8; q++) {
            float4 w = reinterpret_cast<const float4*>(&s1[k * 32])[q];  // uniform LDS.128
            h[q * 4 + 0] = fmaf(xs, w.x, h[q * 4 + 0]);
            h[q * 4 + 1] = fmaf(xs, w.y, h[q * 4 + 1]);
            h[q * 4 + 2] = fmaf(xs, w.z, h[q * 4 + 2]);
            h[q * 4 + 3] = fmaf(xs, w.w, h[q * 4 + 3]);
        }
    }
#pragma unroll
    for (int c = 0; c < 32; c++) h[c] = fmaxf(h[c], 0.0f);

    float o[32];
#pragma unroll
    for (int c = 0; c < 32; c++) o[c] = cbn2[c];
#pragma unroll
    for (int k = 0; k < 32; k++) {
        const float hs = h[k];
#pragma unroll
        for (int q = 0; q < 8; q++) {
            float4 w = reinterpret_cast<const float4*>(&s2[k * 32])[q];
            o[q * 4 + 0] = fmaf(hs, w.x, o[q * 4 + 0]);
            o[q * 4 + 1] = fmaf(hs, w.y, o[q * 4 + 1]);
            o[q * 4 + 2] = fmaf(hs, w.z, o[q * 4 + 2]);
            o[q * 4 + 3] = fmaf(hs, w.w, o[q * 4 + 3]);
        }
    }
#pragma unroll
    for (int q = 0; q < 8; q++)
        reinterpret_cast<float4*>(out)[q] =
            make_float4(fmaxf(o[q * 4], 0.f), fmaxf(o[q * 4 + 1], 0.f),
                        fmaxf(o[q * 4 + 2], 0.f), fmaxf(o[q * 4 + 3], 0.f));
}

// ============ launch ============
extern "C" void kernel_launch(void* const* d_in, const int* in_sizes, int n_in,
                              void* d_out, int out_size) {
    const float* edges = (const float*)d_in[0];
    const float* na    = (const float*)d_in[1];
    const float* nb    = (const float*)d_in[2];
    const float* We1   = (const float*)d_in[3];
    const float* We2   = (const float*)d_in[5];
    const float* Wn1   = (const float*)d_in[7];
    const float* Wn2   = (const float*)d_in[9];

    // biases -> constant memory (lane-uniform access only)
    cudaMemcpyToSymbolAsync(cbe1, d_in[4], 16 * sizeof(float), 0, cudaMemcpyDeviceToDevice);
    cudaMemcpyToSymbolAsync(cbe2, d_in[6], 16 * sizeof(float), 0, cudaMemcpyDeviceToDevice);
    cudaMemcpyToSymbolAsync(cbn1, d_in[8], 32 * sizeof(float), 0, cudaMemcpyDeviceToDevice);
    cudaMemcpyToSymbolAsync(cbn2, d_in[10], 32 * sizeof(float), 0, cudaMemcpyDeviceToDevice);

    float* out_e = (float*)d_out;
    float* out_a = out_e + (size_t)1024 * 1024 * 16;
    float* out_b = out_a + 1024 * 32;

    prep_kernel<<<8, 256>>>(na, nb, We1);

    dim3 grid(4, 128);
    edge_kernel<<<grid, 256>>>(edges, We1, We2, out_e);

    node_kernel<<<16, 128>>>(na, nb, Wn1, Wn2, out_a, out_b);
}